// round 1
// baseline (speedup 1.0000x reference)
#include <cuda_runtime.h>

#define NQ 300
#define CC 256
#define NH 8
#define HD 32
#define HW 1024
#define HID 512

// ---------------- scratch (device globals; no allocation) ----------------
__device__ float g_q[NQ * CC];
__device__ float g_k[HW * CC];
__device__ float g_v[HW * CC];
__device__ float g_s[HID * NQ];     // s[f][q] = W1[f]·ref[q] + b1[f]
__device__ float g_t[HID * HW];     // t[f][k] = W1[f]·key_pos[k]
__device__ float g_w2t[HID * NH];   // W2 transposed: [f][h]
__device__ float g_S[NQ * NH * HW]; // scores (logits*scale + bias), layout [q][h][k]
__device__ float g_ctx[NQ * CC];    // attention context before output proj

// ---------------- prep: s/t tables + W2 transpose ----------------
__global__ void __launch_bounds__(128) prep_kernel(const float* __restrict__ ref,
                                                   const float* __restrict__ W1,
                                                   const float* __restrict__ b1,
                                                   const float* __restrict__ W2) {
    int f = blockIdx.x;
    int tid = threadIdx.x;
    float w1x = W1[2 * f], w1y = W1[2 * f + 1], bb = b1[f];
    for (int k = tid; k < HW; k += 128) {
        int kx = k & 31, ky = k >> 5;
        float px = (kx + 0.5f) * (1.0f / 32.0f);
        float py = (ky + 0.5f) * (1.0f / 32.0f);
        g_t[f * HW + k] = w1x * px + w1y * py;
    }
    for (int q = tid; q < NQ; q += 128) {
        g_s[f * NQ + q] = w1x * ref[2 * q] + w1y * ref[2 * q + 1] + bb;
    }
    if (tid < NH) g_w2t[f * NH + tid] = W2[tid * HID + f];
}

// ---------------- generic small GEMM: out = (A1[+A2]) @ W^T + bias ----------------
// A: [M,256] row-major, W: [256,256] row-major (out = A @ W^T), out: [M,256]
__global__ void __launch_bounds__(256) gemm_bias_kernel(const float* __restrict__ A1,
                                                        const float* __restrict__ A2,
                                                        const float* __restrict__ W,
                                                        const float* __restrict__ bias,
                                                        float* out_ext, int out_sel,
                                                        int a_sel, int M) {
    const float* A = (a_sel == 1) ? g_ctx : A1;
    float* out = (out_sel == 0) ? g_q : (out_sel == 1) ? g_k : (out_sel == 2) ? g_v : out_ext;

    __shared__ float As[16][68];
    __shared__ float Bs[16][68];

    int m0 = blockIdx.x * 64, n0 = blockIdx.y * 64;
    if (m0 >= M) return;

    int t = threadIdx.x;
    int tx = t & 15, ty = t >> 4;
    int r = t >> 2, c4 = t & 3;

    float acc[4][4] = {};

    for (int kc = 0; kc < 256; kc += 16) {
        int gm = m0 + r;
        if (gm >= M) gm = M - 1;
        float4 a = *(const float4*)&A[gm * 256 + kc + c4 * 4];
        if (A2) {
            float4 a2 = *(const float4*)&A2[gm * 256 + kc + c4 * 4];
            a.x += a2.x; a.y += a2.y; a.z += a2.z; a.w += a2.w;
        }
        As[c4 * 4 + 0][r] = a.x;
        As[c4 * 4 + 1][r] = a.y;
        As[c4 * 4 + 2][r] = a.z;
        As[c4 * 4 + 3][r] = a.w;

        float4 b = *(const float4*)&W[(n0 + r) * 256 + kc + c4 * 4];
        Bs[c4 * 4 + 0][r] = b.x;
        Bs[c4 * 4 + 1][r] = b.y;
        Bs[c4 * 4 + 2][r] = b.z;
        Bs[c4 * 4 + 3][r] = b.w;
        __syncthreads();

#pragma unroll
        for (int kk = 0; kk < 16; ++kk) {
            float4 av = *(const float4*)&As[kk][ty * 4];
            float4 bv = *(const float4*)&Bs[kk][tx * 4];
            float aa[4] = {av.x, av.y, av.z, av.w};
            float bb[4] = {bv.x, bv.y, bv.z, bv.w};
#pragma unroll
            for (int i = 0; i < 4; ++i)
#pragma unroll
                for (int j = 0; j < 4; ++j) acc[i][j] = fmaf(aa[i], bb[j], acc[i][j]);
        }
        __syncthreads();
    }

    float4 b4 = *(const float4*)&bias[n0 + tx * 4];
#pragma unroll
    for (int i = 0; i < 4; ++i) {
        int gm = m0 + ty * 4 + i;
        if (gm < M) {
            float4 o;
            o.x = acc[i][0] + b4.x;
            o.y = acc[i][1] + b4.y;
            o.z = acc[i][2] + b4.z;
            o.w = acc[i][3] + b4.w;
            *(float4*)&out[gm * 256 + n0 + tx * 4] = o;
        }
    }
}

// ---------------- score kernel: S = scale * q.k  +  sum_f relu(s-t)*W2 ----------------
// grid: (kt=16, qt=19); block: 256 threads; tile = 16 queries x 64 keys
__global__ void __launch_bounds__(256) score_kernel() {
    __shared__ float smem[64 * 16 + 64 * 64 + 64 * 8]; // 22528 B
    float* bufA = smem;            // [64][16]
    float* bufB = smem + 1024;     // [64][64]
    float* bufC = smem + 5120;     // [64][8]

    int k0 = blockIdx.x * 64;
    int q0 = blockIdx.y * 16;
    int t = threadIdx.x;
    int q = t & 15;       // query within tile
    int kg = t >> 4;      // key group (4 keys each)

    float acc[8][4] = {};

    // ----- phase 1: logits, 4 chunks of 64 channels (2 heads each) -----
#pragma unroll
    for (int c = 0; c < 4; ++c) {
        {
            int qr = t >> 4, d4 = t & 15;
            int gq = q0 + qr;
            if (gq > NQ - 1) gq = NQ - 1;
            float4 a = *(const float4*)&g_q[gq * 256 + c * 64 + d4 * 4];
            bufA[(d4 * 4 + 0) * 16 + qr] = a.x;
            bufA[(d4 * 4 + 1) * 16 + qr] = a.y;
            bufA[(d4 * 4 + 2) * 16 + qr] = a.z;
            bufA[(d4 * 4 + 3) * 16 + qr] = a.w;
#pragma unroll
            for (int j = 0; j < 4; ++j) {
                int idx = t + j * 256;
                int kr = idx >> 4, dd4 = idx & 15;
                float4 b = *(const float4*)&g_k[(k0 + kr) * 256 + c * 64 + dd4 * 4];
                bufB[(dd4 * 4 + 0) * 64 + kr] = b.x;
                bufB[(dd4 * 4 + 1) * 64 + kr] = b.y;
                bufB[(dd4 * 4 + 2) * 64 + kr] = b.z;
                bufB[(dd4 * 4 + 3) * 64 + kr] = b.w;
            }
        }
        __syncthreads();
#pragma unroll
        for (int h2 = 0; h2 < 2; ++h2) {
#pragma unroll 8
            for (int dl = 0; dl < 32; ++dl) {
                int d = h2 * 32 + dl;
                float qv = bufA[d * 16 + q];
                float4 k4 = *(const float4*)&bufB[d * 64 + kg * 4];
                acc[c * 2 + h2][0] = fmaf(qv, k4.x, acc[c * 2 + h2][0]);
                acc[c * 2 + h2][1] = fmaf(qv, k4.y, acc[c * 2 + h2][1]);
                acc[c * 2 + h2][2] = fmaf(qv, k4.z, acc[c * 2 + h2][2]);
                acc[c * 2 + h2][3] = fmaf(qv, k4.w, acc[c * 2 + h2][3]);
            }
        }
        __syncthreads();
    }

    const float scale = 0.17677669529663688f; // 32^-0.5
#pragma unroll
    for (int h = 0; h < 8; ++h)
#pragma unroll
        for (int j = 0; j < 4; ++j) acc[h][j] *= scale;

    // ----- phase 2: CPB bias, 8 chunks of 64 hidden features -----
    for (int fc = 0; fc < 8; ++fc) {
        int f0 = fc * 64;
#pragma unroll
        for (int j = 0; j < 4; ++j) {
            int idx = t + j * 256;
            int fr = idx >> 4, qi = idx & 15;
            int gq = q0 + qi;
            if (gq > NQ - 1) gq = NQ - 1;
            bufA[fr * 16 + qi] = g_s[(f0 + fr) * NQ + gq];
        }
#pragma unroll
        for (int j = 0; j < 4; ++j) {
            int idx = t + j * 256;
            int fr = idx >> 4, k4i = idx & 15;
            float4 b = *(const float4*)&g_t[(f0 + fr) * HW + k0 + k4i * 4];
            *(float4*)&bufB[fr * 64 + k4i * 4] = b;
        }
        for (int idx = t; idx < 512; idx += 256) bufC[idx] = g_w2t[f0 * 8 + idx];
        __syncthreads();

#pragma unroll 4
        for (int fl = 0; fl < 64; ++fl) {
            float sv = bufA[fl * 16 + q];
            float4 t4 = *(const float4*)&bufB[fl * 64 + kg * 4];
            float4 wa = *(const float4*)&bufC[fl * 8];
            float4 wb = *(const float4*)&bufC[fl * 8 + 4];
            float xx[4];
            xx[0] = fmaxf(sv - t4.x, 0.0f);
            xx[1] = fmaxf(sv - t4.y, 0.0f);
            xx[2] = fmaxf(sv - t4.z, 0.0f);
            xx[3] = fmaxf(sv - t4.w, 0.0f);
            float w2v[8] = {wa.x, wa.y, wa.z, wa.w, wb.x, wb.y, wb.z, wb.w};
#pragma unroll
            for (int h = 0; h < 8; ++h)
#pragma unroll
                for (int j = 0; j < 4; ++j) acc[h][j] = fmaf(xx[j], w2v[h], acc[h][j]);
        }
        __syncthreads();
    }

    // ----- store -----
    int gq = q0 + q;
    if (gq < NQ) {
#pragma unroll
        for (int h = 0; h < 8; ++h) {
            float4 o = {acc[h][0], acc[h][1], acc[h][2], acc[h][3]};
            *(float4*)&g_S[(gq * 8 + h) * HW + k0 + kg * 4] = o;
        }
    }
}

// ---------------- softmax + PV: 4 queries per block ----------------
__global__ void __launch_bounds__(256) softmax_pv_kernel() {
    extern __shared__ float p_sm[]; // 4 * 8 * 1024 floats = 128 KB
    __shared__ float rden[32];

    int tid = threadIdx.x;
    int q0 = blockIdx.x * 4;

    // stage S for 4 queries
    const float4* src = (const float4*)&g_S[q0 * 8192];
    float4* dst = (float4*)p_sm;
    for (int i = tid; i < 8192; i += 256) dst[i] = src[i];
    __syncthreads();

    int warp = tid >> 5, lane = tid & 31;
#pragma unroll
    for (int rr = 0; rr < 4; ++rr) {
        int row = rr * 8 + warp; // row = qi*8 + h
        float* p = p_sm + row * 1024;
        float m = -1e30f;
        for (int i = lane; i < 1024; i += 32) m = fmaxf(m, p[i]);
#pragma unroll
        for (int o = 16; o; o >>= 1) m = fmaxf(m, __shfl_xor_sync(0xffffffffu, m, o));
        float s = 0.0f;
        for (int i = lane; i < 1024; i += 32) {
            float e = __expf(p[i] - m);
            p[i] = e;
            s += e;
        }
#pragma unroll
        for (int o = 16; o; o >>= 1) s += __shfl_xor_sync(0xffffffffu, s, o);
        if (lane == 0) rden[row] = 1.0f / s;
    }
    __syncthreads();

    int h = warp, d = lane;
    float a0 = 0.f, a1 = 0.f, a2 = 0.f, a3 = 0.f;
    const float* vp = g_v + h * 32 + d;
#pragma unroll 4
    for (int k = 0; k < 1024; ++k) {
        float vv = vp[k * 256];
        a0 = fmaf(p_sm[(0 * 8 + h) * 1024 + k], vv, a0);
        a1 = fmaf(p_sm[(1 * 8 + h) * 1024 + k], vv, a1);
        a2 = fmaf(p_sm[(2 * 8 + h) * 1024 + k], vv, a2);
        a3 = fmaf(p_sm[(3 * 8 + h) * 1024 + k], vv, a3);
    }
    g_ctx[(q0 + 0) * 256 + h * 32 + d] = a0 * rden[0 * 8 + h];
    g_ctx[(q0 + 1) * 256 + h * 32 + d] = a1 * rden[1 * 8 + h];
    g_ctx[(q0 + 2) * 256 + h * 32 + d] = a2 * rden[2 * 8 + h];
    g_ctx[(q0 + 3) * 256 + h * 32 + d] = a3 * rden[3 * 8 + h];
}

// ---------------- launch ----------------
extern "C" void kernel_launch(void* const* d_in, const int* in_sizes, int n_in,
                              void* d_out, int out_size) {
    const float* raw_query = (const float*)d_in[0];
    const float* query_pos = (const float*)d_in[1];
    const float* ref_pts   = (const float*)d_in[2];
    const float* raw_src   = (const float*)d_in[3];
    const float* src_pos   = (const float*)d_in[4];
    const float* Wq = (const float*)d_in[5];
    const float* bq = (const float*)d_in[6];
    const float* Wk = (const float*)d_in[7];
    const float* bk = (const float*)d_in[8];
    const float* Wv = (const float*)d_in[9];
    const float* bv = (const float*)d_in[10];
    const float* Wo = (const float*)d_in[11];
    const float* bo = (const float*)d_in[12];
    const float* W1 = (const float*)d_in[13];
    const float* b1 = (const float*)d_in[14];
    const float* W2 = (const float*)d_in[15];
    float* out = (float*)d_out;

    // prep tables
    prep_kernel<<<512, 128>>>(ref_pts, W1, b1, W2);

    // projections (fused input add)
    gemm_bias_kernel<<<dim3(5, 4), 256>>>(raw_query, query_pos, Wq, bq, nullptr, 0, 0, NQ);
    gemm_bias_kernel<<<dim3(16, 4), 256>>>(raw_src, src_pos, Wk, bk, nullptr, 1, 0, HW);
    gemm_bias_kernel<<<dim3(16, 4), 256>>>(raw_src, src_pos, Wv, bv, nullptr, 2, 0, HW);

    // scores: logits + cpb bias
    score_kernel<<<dim3(16, 19), 256>>>();

    // softmax + PV
    cudaFuncSetAttribute(softmax_pv_kernel, cudaFuncAttributeMaxDynamicSharedMemorySize,
                         4 * 8 * 1024 * (int)sizeof(float));
    softmax_pv_kernel<<<75, 256, 4 * 8 * 1024 * sizeof(float)>>>();

    // output projection
    gemm_bias_kernel<<<dim3(5, 4), 256>>>(nullptr, nullptr, Wo, bo, out, 3, 1, NQ);
}